// round 8
// baseline (speedup 1.0000x reference)
#include <cuda_runtime.h>
#include <cstdint>

// MaskedNormalize fused persistent kernel, round 5.
// x [16, 4, 1024, 1024] fp32. valid = (x != 0).
// Invalid entries are exactly 0 => sum(x*v)=sum(x), sum(x^2*v)=sum(x^2);
// only the count needs the predicate.
//
// 144 blocks (9 per batch, uneven chunks) x 1024 threads, all co-resident
// (1 block/SM, 144 <= 148 SMs) -> spin barrier is deadlock-free.
// Phase 1: per-block partial (S1,S2,n) over its chunk (normal cached loads).
// Global barrier (monotonic arrival counter; graph replays serialize so no
// reset is needed). Phase 2: normalize own chunk in REVERSE order with
// streaming loads (ld.cs) and streaming stores (st.cs) so output writes do
// not evict the phase-1 L2-resident tail of x.

#define BATCHES     16
#define PER_BATCH   (4u * 1024u * 1024u)      // elements per batch
#define VEC_PER_B   (PER_BATCH / 4u)          // float4 per batch = 1,048,576

#define BLKS_PER_B  9
#define GRID        (BATCHES * BLKS_PER_B)    // 144 blocks
#define THREADS     1024

#define CHUNK_BASE  (VEC_PER_B / BLKS_PER_B)  // 116508
#define CHUNK_REM   (VEC_PER_B % BLKS_PER_B)  // 4

#define EPS         1e-5f

// Deterministic scratch: every slot written every launch.
__device__ float g_s1[GRID];
__device__ float g_s2[GRID];
__device__ float g_cn[GRID];
// Monotonic arrival counter; never reset (u64 cannot overflow in practice).
__device__ unsigned long long g_arrive = 0ULL;

__device__ __forceinline__ float4 ldcs_f4(const float4* p) {
    float4 v;
    asm volatile("ld.global.cs.v4.f32 {%0,%1,%2,%3}, [%4];"
                 : "=f"(v.x), "=f"(v.y), "=f"(v.z), "=f"(v.w) : "l"(p));
    return v;
}
__device__ __forceinline__ void stcs_f4(float4* p, float4 v) {
    asm volatile("st.global.cs.v4.f32 [%0], {%1,%2,%3,%4};"
                 :: "l"(p), "f"(v.x), "f"(v.y), "f"(v.z), "f"(v.w) : "memory");
}

__global__ __launch_bounds__(THREADS) void mn_fused_kernel(const float* __restrict__ x,
                                                           float* __restrict__ out)
{
    const int bid   = blockIdx.x;
    const int batch = bid / BLKS_PER_B;
    const int sub   = bid % BLKS_PER_B;

    // Uneven chunk split: first CHUNK_REM blocks get one extra float4.
    const unsigned start = (unsigned)sub * CHUNK_BASE + (unsigned)min(sub, CHUNK_REM);
    const unsigned count = CHUNK_BASE + (sub < CHUNK_REM ? 1u : 0u);

    const float4* __restrict__ xb =
        reinterpret_cast<const float4*>(x + (size_t)batch * PER_BATCH) + start;
    float4* __restrict__ ob =
        reinterpret_cast<float4*>(out + (size_t)batch * PER_BATCH) + start;

    // ---------------- Phase 1: partial sums over this block's chunk --------
    float s1 = 0.f, s2 = 0.f;
    int   cnt = 0;

    #pragma unroll 4
    for (unsigned j = threadIdx.x; j < count; j += THREADS) {
        float4 v = xb[j];
        s1  += (v.x + v.y) + (v.z + v.w);
        s2  += (v.x * v.x + v.y * v.y) + (v.z * v.z + v.w * v.w);
        cnt += (v.x != 0.f) + (v.y != 0.f) + (v.z != 0.f) + (v.w != 0.f);
    }

    // warp reduce
    #pragma unroll
    for (int off = 16; off > 0; off >>= 1) {
        s1  += __shfl_xor_sync(0xFFFFFFFFu, s1, off);
        s2  += __shfl_xor_sync(0xFFFFFFFFu, s2, off);
        cnt += __shfl_xor_sync(0xFFFFFFFFu, cnt, off);
    }

    __shared__ float sh1[THREADS / 32];
    __shared__ float sh2[THREADS / 32];
    __shared__ int   shc[THREADS / 32];
    __shared__ float2 sh_stats;   // {mean, rstd} broadcast after barrier

    const int lane = threadIdx.x & 31;
    const int wid  = threadIdx.x >> 5;
    if (lane == 0) { sh1[wid] = s1; sh2[wid] = s2; shc[wid] = cnt; }
    __syncthreads();

    if (wid == 0) {
        s1  = (lane < THREADS / 32) ? sh1[lane] : 0.f;
        s2  = (lane < THREADS / 32) ? sh2[lane] : 0.f;
        cnt = (lane < THREADS / 32) ? shc[lane] : 0;
        #pragma unroll
        for (int off = 16; off > 0; off >>= 1) {
            s1  += __shfl_xor_sync(0xFFFFFFFFu, s1, off);
            s2  += __shfl_xor_sync(0xFFFFFFFFu, s2, off);
            cnt += __shfl_xor_sync(0xFFFFFFFFu, cnt, off);
        }
    }

    // ---------------- Global barrier + per-batch stats ---------------------
    if (threadIdx.x == 0) {
        g_s1[bid] = s1;
        g_s2[bid] = s2;
        g_cn[bid] = (float)cnt;
        __threadfence();

        unsigned long long my = atomicAdd(&g_arrive, 1ULL);
        unsigned long long target = (my / GRID) * GRID + (unsigned long long)GRID;
        for (;;) {
            unsigned long long cur;
            asm volatile("ld.global.acquire.gpu.u64 %0, [%1];"
                         : "=l"(cur) : "l"(&g_arrive));
            if (cur >= target) break;
        }

        // All partials visible; compute this batch's stats in double.
        double S1 = 0.0, S2 = 0.0, n = 0.0;
        #pragma unroll
        for (int k = 0; k < BLKS_PER_B; k++) {
            S1 += (double)g_s1[batch * BLKS_PER_B + k];
            S2 += (double)g_s2[batch * BLKS_PER_B + k];
            n  += (double)g_cn[batch * BLKS_PER_B + k];
        }
        double mean = S1 / n;
        double var  = (S2 - S1 * S1 / n) / (n - 1.0);
        float  rstd = 1.0f / (sqrtf((float)var) + EPS);
        sh_stats = make_float2((float)mean, rstd);
    }
    __syncthreads();

    const float mean = sh_stats.x;
    const float rstd = sh_stats.y;

    // ---------------- Phase 2: normalize own chunk, REVERSE order ----------
    // The tail of this chunk was read most recently in phase 1 -> likely
    // still L2-resident. Streaming stores (st.cs) keep output writes from
    // evicting it; streaming loads (ld.cs) evict x after its last use.
    const unsigned iters = (count + THREADS - 1) / THREADS;
    for (int it = (int)iters - 1; it >= 0; --it) {
        unsigned j = (unsigned)it * THREADS + threadIdx.x;
        if (j < count) {
            float4 v = ldcs_f4(xb + j);
            float4 o;
            o.x = (v.x != 0.f) ? (v.x - mean) * rstd : 0.f;
            o.y = (v.y != 0.f) ? (v.y - mean) * rstd : 0.f;
            o.z = (v.z != 0.f) ? (v.z - mean) * rstd : 0.f;
            o.w = (v.w != 0.f) ? (v.w - mean) * rstd : 0.f;
            stcs_f4(ob + j, o);
        }
    }
}

extern "C" void kernel_launch(void* const* d_in, const int* in_sizes, int n_in,
                              void* d_out, int out_size)
{
    const float* x   = (const float*)d_in[0];
    float*       out = (float*)d_out;
    mn_fused_kernel<<<GRID, THREADS>>>(x, out);
}

// round 10
// speedup vs baseline: 1.1803x; 1.1803x over previous
#include <cuda_runtime.h>
#include <cstdint>

// MaskedNormalize, round 9: back to split kernels.
// x [16, 4, 1024, 1024] fp32. valid = (x != 0).
// Invalid entries are exactly 0 => sum(x*v)=sum(x), sum(x^2*v)=sum(x^2);
// only the count needs the predicate.
//
// Kernel 1 (proven at read roofline, 6.55 TB/s): 2048 blocks x 256 threads,
// per-block partial (S1,S2,n) into fixed slots (deterministic, no atomics).
// Kernel 2: 2048 blocks x 256 threads; each block first reduces its batch's
// 128 partials (L2-hit reads, ~3KB) to (mean, rstd), then normalizes its
// 8192-float4 chunk with a front-batched unroll-4 body (4 independent
// LDG.128 in flight per thread). Plain cached loads/stores -- no cache
// hints (measured: .cs cut BW from 5.8 to 4.5 TB/s on this chip).

#define BATCHES     16
#define PER_BATCH   (4u * 1024u * 1024u)     // elements per batch
#define VEC_PER_B   (PER_BATCH / 4u)         // float4 per batch = 1,048,576

#define RBPB        128                      // reduction blocks per batch
#define RTHREADS    256
#define VEC_PER_RBLK (VEC_PER_B / RBPB)      // 8192 float4

#define NBPB        128                      // normalize blocks per batch
#define NTHREADS    256
#define VEC_PER_NBLK (VEC_PER_B / NBPB)      // 8192 float4
#define NUNROLL     4
#define NITERS      (VEC_PER_NBLK / (NTHREADS * NUNROLL))  // 8

#define EPS         1e-5f

// Deterministic scratch: every slot written every launch (no zeroing needed).
__device__ float g_s1[BATCHES * RBPB];
__device__ float g_s2[BATCHES * RBPB];
__device__ float g_cn[BATCHES * RBPB];

// ---------------------------------------------------------------------------
// Kernel 1: per-block partial sums (S1, S2, count) over contiguous chunks.
// Grid: (RBPB, BATCHES), RTHREADS threads.  [unchanged from R1: 6.55 TB/s]
// ---------------------------------------------------------------------------
__global__ __launch_bounds__(RTHREADS) void mn_reduce_kernel(const float* __restrict__ x)
{
    const int b   = blockIdx.y;
    const int blk = blockIdx.x;
    const float4* __restrict__ xb =
        reinterpret_cast<const float4*>(x + (size_t)b * PER_BATCH) + (size_t)blk * VEC_PER_RBLK;

    float s1 = 0.f, s2 = 0.f;
    int   cnt = 0;

    #pragma unroll 4
    for (unsigned j = threadIdx.x; j < VEC_PER_RBLK; j += RTHREADS) {
        float4 v = xb[j];
        s1 += (v.x + v.y) + (v.z + v.w);
        s2 += (v.x * v.x + v.y * v.y) + (v.z * v.z + v.w * v.w);
        cnt += (v.x != 0.f) + (v.y != 0.f) + (v.z != 0.f) + (v.w != 0.f);
    }

    #pragma unroll
    for (int off = 16; off > 0; off >>= 1) {
        s1  += __shfl_xor_sync(0xFFFFFFFFu, s1, off);
        s2  += __shfl_xor_sync(0xFFFFFFFFu, s2, off);
        cnt += __shfl_xor_sync(0xFFFFFFFFu, cnt, off);
    }

    __shared__ float sh1[RTHREADS / 32];
    __shared__ float sh2[RTHREADS / 32];
    __shared__ int   shc[RTHREADS / 32];
    const int lane = threadIdx.x & 31;
    const int wid  = threadIdx.x >> 5;
    if (lane == 0) { sh1[wid] = s1; sh2[wid] = s2; shc[wid] = cnt; }
    __syncthreads();

    if (wid == 0) {
        s1  = (lane < RTHREADS / 32) ? sh1[lane] : 0.f;
        s2  = (lane < RTHREADS / 32) ? sh2[lane] : 0.f;
        cnt = (lane < RTHREADS / 32) ? shc[lane] : 0;
        #pragma unroll
        for (int off = 4; off > 0; off >>= 1) {
            s1  += __shfl_xor_sync(0xFFFFFFFFu, s1, off);
            s2  += __shfl_xor_sync(0xFFFFFFFFu, s2, off);
            cnt += __shfl_xor_sync(0xFFFFFFFFu, cnt, off);
        }
        if (lane == 0) {
            g_s1[b * RBPB + blk] = s1;
            g_s2[b * RBPB + blk] = s2;
            g_cn[b * RBPB + blk] = (float)cnt;
        }
    }
}

// ---------------------------------------------------------------------------
// Kernel 2: stats (per block, redundant, L2-hit) + normalize.
// Grid: (NBPB, BATCHES), NTHREADS threads.
// ---------------------------------------------------------------------------
__global__ __launch_bounds__(NTHREADS) void mn_normalize_kernel(const float* __restrict__ x,
                                                                float* __restrict__ out)
{
    const int b   = blockIdx.y;
    const int blk = blockIdx.x;

    // ---- per-block batch stats from the 128 partials (double precision) ----
    __shared__ double d1[RBPB], d2[RBPB], dc[RBPB];
    __shared__ float2 sh_stats;

    const int t = threadIdx.x;
    if (t < RBPB) {
        d1[t] = (double)g_s1[b * RBPB + t];
        d2[t] = (double)g_s2[b * RBPB + t];
        dc[t] = (double)g_cn[b * RBPB + t];
    }
    __syncthreads();

    #pragma unroll
    for (int off = RBPB / 2; off > 0; off >>= 1) {
        if (t < off) {
            d1[t] += d1[t + off];
            d2[t] += d2[t + off];
            dc[t] += dc[t + off];
        }
        __syncthreads();
    }

    if (t == 0) {
        double S1 = d1[0], S2 = d2[0], n = dc[0];
        double mean = S1 / n;
        double var  = (S2 - S1 * S1 / n) / (n - 1.0);
        float  rstd = 1.0f / (sqrtf((float)var) + EPS);
        sh_stats = make_float2((float)mean, rstd);
    }
    __syncthreads();

    const float mean = sh_stats.x;
    const float rstd = sh_stats.y;

    // ---- normalize this block's chunk: front-batched unroll-4 ----
    const float4* __restrict__ xb =
        reinterpret_cast<const float4*>(x + (size_t)b * PER_BATCH) + (size_t)blk * VEC_PER_NBLK;
    float4* __restrict__ ob =
        reinterpret_cast<float4*>(out + (size_t)b * PER_BATCH) + (size_t)blk * VEC_PER_NBLK;

    #pragma unroll 2
    for (int it = 0; it < NITERS; it++) {
        const unsigned base = (unsigned)it * (NTHREADS * NUNROLL) + threadIdx.x;

        // 4 independent loads issued back-to-back (MLP_p1 = 4)
        float4 v0 = xb[base + 0 * NTHREADS];
        float4 v1 = xb[base + 1 * NTHREADS];
        float4 v2 = xb[base + 2 * NTHREADS];
        float4 v3 = xb[base + 3 * NTHREADS];

        float4 o0, o1, o2, o3;
        o0.x = (v0.x != 0.f) ? (v0.x - mean) * rstd : 0.f;
        o0.y = (v0.y != 0.f) ? (v0.y - mean) * rstd : 0.f;
        o0.z = (v0.z != 0.f) ? (v0.z - mean) * rstd : 0.f;
        o0.w = (v0.w != 0.f) ? (v0.w - mean) * rstd : 0.f;
        o1.x = (v1.x != 0.f) ? (v1.x - mean) * rstd : 0.f;
        o1.y = (v1.y != 0.f) ? (v1.y - mean) * rstd : 0.f;
        o1.z = (v1.z != 0.f) ? (v1.z - mean) * rstd : 0.f;
        o1.w = (v1.w != 0.f) ? (v1.w - mean) * rstd : 0.f;
        o2.x = (v2.x != 0.f) ? (v2.x - mean) * rstd : 0.f;
        o2.y = (v2.y != 0.f) ? (v2.y - mean) * rstd : 0.f;
        o2.z = (v2.z != 0.f) ? (v2.z - mean) * rstd : 0.f;
        o2.w = (v2.w != 0.f) ? (v2.w - mean) * rstd : 0.f;
        o3.x = (v3.x != 0.f) ? (v3.x - mean) * rstd : 0.f;
        o3.y = (v3.y != 0.f) ? (v3.y - mean) * rstd : 0.f;
        o3.z = (v3.z != 0.f) ? (v3.z - mean) * rstd : 0.f;
        o3.w = (v3.w != 0.f) ? (v3.w - mean) * rstd : 0.f;

        ob[base + 0 * NTHREADS] = o0;
        ob[base + 1 * NTHREADS] = o1;
        ob[base + 2 * NTHREADS] = o2;
        ob[base + 3 * NTHREADS] = o3;
    }
}

// ---------------------------------------------------------------------------
extern "C" void kernel_launch(void* const* d_in, const int* in_sizes, int n_in,
                              void* d_out, int out_size)
{
    const float* x   = (const float*)d_in[0];
    float*       out = (float*)d_out;

    dim3 rgrid(RBPB, BATCHES);
    mn_reduce_kernel<<<rgrid, RTHREADS>>>(x);

    dim3 ngrid(NBPB, BATCHES);
    mn_normalize_kernel<<<ngrid, NTHREADS>>>(x, out);
}

// round 12
// speedup vs baseline: 1.2316x; 1.0434x over previous
#include <cuda_runtime.h>
#include <cstdint>

// MaskedNormalize, round 11: split kernels + PDL overlap.
// x [16, 4, 1024, 1024] fp32. valid = (x != 0).
// Invalid entries are exactly 0 => sum(x*v)=sum(x), sum(x^2*v)=sum(x^2);
// only the count needs the predicate.
//
// Kernel 1 (read roofline, 6.55 TB/s): 2048 x 256, per-block partials
// (S1,S2,n) into fixed slots; each block triggers programmatic launch
// completion after publishing (post-threadfence).
// Kernel 2 (mixed ceiling ~5.9 TB/s): 2048 x 256; launched with
// programmaticStreamSerializationAllowed so it overlaps the reduce tail.
// Each block prefetches its first 4 independent LDG.128 (stats-independent),
// THEN cudaGridDependencySynchronize(), reads the 128 partials (L2-hit),
// computes (mean, rstd), normalizes. Plain cached loads/stores (.cs measured
// slower on this chip).

#define BATCHES     16
#define PER_BATCH   (4u * 1024u * 1024u)     // elements per batch
#define VEC_PER_B   (PER_BATCH / 4u)         // float4 per batch = 1,048,576

#define RBPB        128                      // reduction blocks per batch
#define RTHREADS    256
#define VEC_PER_RBLK (VEC_PER_B / RBPB)      // 8192 float4

#define NBPB        128                      // normalize blocks per batch
#define NTHREADS    256
#define VEC_PER_NBLK (VEC_PER_B / NBPB)      // 8192 float4
#define NUNROLL     4
#define NITERS      (VEC_PER_NBLK / (NTHREADS * NUNROLL))  // 8

#define EPS         1e-5f

// Deterministic scratch: every slot written every launch (no zeroing needed).
__device__ float g_s1[BATCHES * RBPB];
__device__ float g_s2[BATCHES * RBPB];
__device__ float g_cn[BATCHES * RBPB];

// ---------------------------------------------------------------------------
// Kernel 1: per-block partial sums (S1, S2, count) over contiguous chunks.
// ---------------------------------------------------------------------------
__global__ __launch_bounds__(RTHREADS) void mn_reduce_kernel(const float* __restrict__ x)
{
    const int b   = blockIdx.y;
    const int blk = blockIdx.x;
    const float4* __restrict__ xb =
        reinterpret_cast<const float4*>(x + (size_t)b * PER_BATCH) + (size_t)blk * VEC_PER_RBLK;

    float s1 = 0.f, s2 = 0.f;
    int   cnt = 0;

    #pragma unroll 4
    for (unsigned j = threadIdx.x; j < VEC_PER_RBLK; j += RTHREADS) {
        float4 v = xb[j];
        s1 += (v.x + v.y) + (v.z + v.w);
        s2 += (v.x * v.x + v.y * v.y) + (v.z * v.z + v.w * v.w);
        cnt += (v.x != 0.f) + (v.y != 0.f) + (v.z != 0.f) + (v.w != 0.f);
    }

    #pragma unroll
    for (int off = 16; off > 0; off >>= 1) {
        s1  += __shfl_xor_sync(0xFFFFFFFFu, s1, off);
        s2  += __shfl_xor_sync(0xFFFFFFFFu, s2, off);
        cnt += __shfl_xor_sync(0xFFFFFFFFu, cnt, off);
    }

    __shared__ float sh1[RTHREADS / 32];
    __shared__ float sh2[RTHREADS / 32];
    __shared__ int   shc[RTHREADS / 32];
    const int lane = threadIdx.x & 31;
    const int wid  = threadIdx.x >> 5;
    if (lane == 0) { sh1[wid] = s1; sh2[wid] = s2; shc[wid] = cnt; }
    __syncthreads();

    if (wid == 0) {
        s1  = (lane < RTHREADS / 32) ? sh1[lane] : 0.f;
        s2  = (lane < RTHREADS / 32) ? sh2[lane] : 0.f;
        cnt = (lane < RTHREADS / 32) ? shc[lane] : 0;
        #pragma unroll
        for (int off = 4; off > 0; off >>= 1) {
            s1  += __shfl_xor_sync(0xFFFFFFFFu, s1, off);
            s2  += __shfl_xor_sync(0xFFFFFFFFu, s2, off);
            cnt += __shfl_xor_sync(0xFFFFFFFFu, cnt, off);
        }
        if (lane == 0) {
            g_s1[b * RBPB + blk] = s1;
            g_s2[b * RBPB + blk] = s2;
            g_cn[b * RBPB + blk] = (float)cnt;
            __threadfence();
            cudaTriggerProgrammaticLaunchCompletion();
        }
    }
}

// ---------------------------------------------------------------------------
// Kernel 2: prefetch -> grid-dependency sync -> stats -> normalize.
// ---------------------------------------------------------------------------
__global__ __launch_bounds__(NTHREADS) void mn_normalize_kernel(const float* __restrict__ x,
                                                                float* __restrict__ out)
{
    const int b   = blockIdx.y;
    const int blk = blockIdx.x;

    const float4* __restrict__ xb =
        reinterpret_cast<const float4*>(x + (size_t)b * PER_BATCH) + (size_t)blk * VEC_PER_NBLK;
    float4* __restrict__ ob =
        reinterpret_cast<float4*>(out + (size_t)b * PER_BATCH) + (size_t)blk * VEC_PER_NBLK;

    // ---- prefetch iteration 0 (independent of the reduce's results) ----
    float4 p0 = xb[threadIdx.x + 0 * NTHREADS];
    float4 p1 = xb[threadIdx.x + 1 * NTHREADS];
    float4 p2 = xb[threadIdx.x + 2 * NTHREADS];
    float4 p3 = xb[threadIdx.x + 3 * NTHREADS];

    // ---- wait for the reduce grid's partials to be visible ----
    cudaGridDependencySynchronize();

    // ---- per-block batch stats from the 128 partials (double precision) ----
    __shared__ double d1[RBPB], d2[RBPB], dc[RBPB];
    __shared__ float2 sh_stats;

    const int t = threadIdx.x;
    if (t < RBPB) {
        d1[t] = (double)g_s1[b * RBPB + t];
        d2[t] = (double)g_s2[b * RBPB + t];
        dc[t] = (double)g_cn[b * RBPB + t];
    }
    __syncthreads();

    #pragma unroll
    for (int off = RBPB / 2; off > 0; off >>= 1) {
        if (t < off) {
            d1[t] += d1[t + off];
            d2[t] += d2[t + off];
            dc[t] += dc[t + off];
        }
        __syncthreads();
    }

    if (t == 0) {
        double S1 = d1[0], S2 = d2[0], n = dc[0];
        double mean = S1 / n;
        double var  = (S2 - S1 * S1 / n) / (n - 1.0);
        float  rstd = 1.0f / (sqrtf((float)var) + EPS);
        sh_stats = make_float2((float)mean, rstd);
    }
    __syncthreads();

    const float mean = sh_stats.x;
    const float rstd = sh_stats.y;

    // ---- iteration 0 from prefetched registers ----
    {
        float4 o0, o1, o2, o3;
        o0.x = (p0.x != 0.f) ? (p0.x - mean) * rstd : 0.f;
        o0.y = (p0.y != 0.f) ? (p0.y - mean) * rstd : 0.f;
        o0.z = (p0.z != 0.f) ? (p0.z - mean) * rstd : 0.f;
        o0.w = (p0.w != 0.f) ? (p0.w - mean) * rstd : 0.f;
        o1.x = (p1.x != 0.f) ? (p1.x - mean) * rstd : 0.f;
        o1.y = (p1.y != 0.f) ? (p1.y - mean) * rstd : 0.f;
        o1.z = (p1.z != 0.f) ? (p1.z - mean) * rstd : 0.f;
        o1.w = (p1.w != 0.f) ? (p1.w - mean) * rstd : 0.f;
        o2.x = (p2.x != 0.f) ? (p2.x - mean) * rstd : 0.f;
        o2.y = (p2.y != 0.f) ? (p2.y - mean) * rstd : 0.f;
        o2.z = (p2.z != 0.f) ? (p2.z - mean) * rstd : 0.f;
        o2.w = (p2.w != 0.f) ? (p2.w - mean) * rstd : 0.f;
        o3.x = (p3.x != 0.f) ? (p3.x - mean) * rstd : 0.f;
        o3.y = (p3.y != 0.f) ? (p3.y - mean) * rstd : 0.f;
        o3.z = (p3.z != 0.f) ? (p3.z - mean) * rstd : 0.f;
        o3.w = (p3.w != 0.f) ? (p3.w - mean) * rstd : 0.f;
        ob[threadIdx.x + 0 * NTHREADS] = o0;
        ob[threadIdx.x + 1 * NTHREADS] = o1;
        ob[threadIdx.x + 2 * NTHREADS] = o2;
        ob[threadIdx.x + 3 * NTHREADS] = o3;
    }

    // ---- iterations 1..NITERS-1: front-batched unroll-4 ----
    #pragma unroll 2
    for (int it = 1; it < NITERS; it++) {
        const unsigned base = (unsigned)it * (NTHREADS * NUNROLL) + threadIdx.x;

        float4 v0 = xb[base + 0 * NTHREADS];
        float4 v1 = xb[base + 1 * NTHREADS];
        float4 v2 = xb[base + 2 * NTHREADS];
        float4 v3 = xb[base + 3 * NTHREADS];

        float4 o0, o1, o2, o3;
        o0.x = (v0.x != 0.f) ? (v0.x - mean) * rstd : 0.f;
        o0.y = (v0.y != 0.f) ? (v0.y - mean) * rstd : 0.f;
        o0.z = (v0.z != 0.f) ? (v0.z - mean) * rstd : 0.f;
        o0.w = (v0.w != 0.f) ? (v0.w - mean) * rstd : 0.f;
        o1.x = (v1.x != 0.f) ? (v1.x - mean) * rstd : 0.f;
        o1.y = (v1.y != 0.f) ? (v1.y - mean) * rstd : 0.f;
        o1.z = (v1.z != 0.f) ? (v1.z - mean) * rstd : 0.f;
        o1.w = (v1.w != 0.f) ? (v1.w - mean) * rstd : 0.f;
        o2.x = (v2.x != 0.f) ? (v2.x - mean) * rstd : 0.f;
        o2.y = (v2.y != 0.f) ? (v2.y - mean) * rstd : 0.f;
        o2.z = (v2.z != 0.f) ? (v2.z - mean) * rstd : 0.f;
        o2.w = (v2.w != 0.f) ? (v2.w - mean) * rstd : 0.f;
        o3.x = (v3.x != 0.f) ? (v3.x - mean) * rstd : 0.f;
        o3.y = (v3.y != 0.f) ? (v3.y - mean) * rstd : 0.f;
        o3.z = (v3.z != 0.f) ? (v3.z - mean) * rstd : 0.f;
        o3.w = (v3.w != 0.f) ? (v3.w - mean) * rstd : 0.f;

        ob[base + 0 * NTHREADS] = o0;
        ob[base + 1 * NTHREADS] = o1;
        ob[base + 2 * NTHREADS] = o2;
        ob[base + 3 * NTHREADS] = o3;
    }
}

// ---------------------------------------------------------------------------
extern "C" void kernel_launch(void* const* d_in, const int* in_sizes, int n_in,
                              void* d_out, int out_size)
{
    const float* x   = (const float*)d_in[0];
    float*       out = (float*)d_out;

    dim3 rgrid(RBPB, BATCHES);
    mn_reduce_kernel<<<rgrid, RTHREADS>>>(x);

    dim3 ngrid(NBPB, BATCHES);

    // Launch normalize with programmatic stream serialization (PDL) so its
    // first wave overlaps the reduce kernel's drain tail.
    cudaLaunchConfig_t cfg = {};
    cfg.gridDim  = ngrid;
    cfg.blockDim = dim3(NTHREADS, 1, 1);
    cfg.dynamicSmemBytes = 0;
    cfg.stream = 0;
    cudaLaunchAttribute attrs[1];
    attrs[0].id = cudaLaunchAttributeProgrammaticStreamSerialization;
    attrs[0].val.programmaticStreamSerializationAllowed = 1;
    cfg.attrs = attrs;
    cfg.numAttrs = 1;

    cudaError_t err = cudaLaunchKernelEx(&cfg, mn_normalize_kernel, x, out);
    if (err != cudaSuccess) {
        // Fallback: plain serialized launch (grid sync then degenerates to
        // a no-op after full completion of the reduce kernel).
        mn_normalize_kernel<<<ngrid, NTHREADS>>>(x, out);
    }
}